// round 1
// baseline (speedup 1.0000x reference)
#include <cuda_runtime.h>
#include <math.h>

#define B_    1024
#define NI_   64
#define NN_   8256
#define E_    131072
#define NOUT_ 64
#define MAXP2 512      // per-output-node pass-2 edge cap (expected ~16, Poisson)
#define MAXP1 64       // per-needed-node pass-1 (src<NI) edge cap (expected ~0.12)
#define TPB   256

// ---------------- scratch (__device__ globals; no allocation allowed) ----------------
__device__ int           g_p2_cnt[NOUT_];
__device__ int           g_p2_src[NOUT_ * MAXP2];
__device__ float         g_p2_w  [NOUT_ * MAXP2];
__device__ unsigned char g_needed[NN_];        // internal node appears as pass-2 src
__device__ unsigned char g_has_in[NN_];        // node has any incoming edge
__device__ int           g_node_slot[NN_];     // node -> compacted slot
__device__ int           g_needed_list[NN_];   // slot -> node
__device__ int           g_needed_cnt;
__device__ int           g_p1_cnt[NN_];        // per slot
__device__ int           g_p1_src[NN_ * MAXP1];
__device__ float         g_p1_w  [NN_ * MAXP1];
__device__ float         g_state1[NN_ * B_];   // pass-1 activations, [slot][b] (33.8 MB worst case)
__device__ float         g_inT   [NI_ * B_];   // transposed inputs, [feature][b]

// ---------------- kernels ----------------
__global__ void k_zero() {
    int i = blockIdx.x * blockDim.x + threadIdx.x;
    if (i < NN_) { g_needed[i] = 0; g_has_in[i] = 0; g_p1_cnt[i] = 0; }
    if (i < NOUT_) g_p2_cnt[i] = 0;
    if (i == 0)    g_needed_cnt = 0;
}

__global__ void k_transpose(const float* __restrict__ in) {
    int i = blockIdx.x * blockDim.x + threadIdx.x;   // i = c*B + r
    if (i < NI_ * B_) {
        int c = i / B_, r = i % B_;
        g_inT[i] = in[r * NI_ + c];
    }
}

// scan all edges: has_in flags, collect pass-2 edges (dst<64), mark needed internal srcs
__global__ void k_scan1(const int* __restrict__ src, const int* __restrict__ dst,
                        const float* __restrict__ w) {
    int e = blockIdx.x * blockDim.x + threadIdx.x;
    if (e >= E_) return;
    int d = dst[e];
    g_has_in[d] = 1;
    if (d < NOUT_) {
        int s   = src[e];
        int pos = atomicAdd(&g_p2_cnt[d], 1);
        if (pos < MAXP2) {
            g_p2_src[d * MAXP2 + pos] = s;
            g_p2_w  [d * MAXP2 + pos] = w[e];
        }
        if (s >= NI_) g_needed[s - NI_] = 1;
    }
}

__global__ void k_compact() {
    int j = blockIdx.x * blockDim.x + threadIdx.x;
    if (j < NN_ && g_needed[j]) {
        int slot = atomicAdd(&g_needed_cnt, 1);
        g_node_slot[j]      = slot;
        g_needed_list[slot] = j;
    }
}

// scan all edges: collect pass-1 input edges (src<NI) feeding needed nodes
__global__ void k_scan2(const int* __restrict__ src, const int* __restrict__ dst,
                        const float* __restrict__ w) {
    int e = blockIdx.x * blockDim.x + threadIdx.x;
    if (e >= E_) return;
    int s = src[e];
    if (s < NI_) {
        int d = dst[e];
        if (g_needed[d]) {
            int slot = g_node_slot[d];
            int pos  = atomicAdd(&g_p1_cnt[slot], 1);
            if (pos < MAXP1) {
                g_p1_src[slot * MAXP1 + pos] = s;
                g_p1_w  [slot * MAXP1 + pos] = w[e];
            }
        }
    }
}

// pass 1: compute state1 for needed nodes only (state0 = 0 => only src<NI edges matter)
__global__ void __launch_bounds__(TPB) k_pass1(const float* __restrict__ bias,
                                               const float* __restrict__ resp) {
    int slot = blockIdx.x;
    if (slot >= g_needed_cnt) return;
    int j = g_needed_list[slot];
    float* row = g_state1 + (size_t)slot * B_;
    int t = threadIdx.x;
    if (!g_has_in[j]) {                        // no incoming edges -> exactly 0
        for (int b = t; b < B_; b += TPB) row[b] = 0.f;
        return;
    }
    int k = g_p1_cnt[slot]; if (k > MAXP1) k = MAXP1;
    __shared__ int   ss[MAXP1];
    __shared__ float sw[MAXP1];
    if (t < k) { ss[t] = g_p1_src[slot * MAXP1 + t]; sw[t] = g_p1_w[slot * MAXP1 + t]; }
    __syncthreads();
    float bj = bias[j], rj = resp[j];
    for (int b = t; b < B_; b += TPB) {
        float agg = 0.f;
        #pragma unroll 4
        for (int i = 0; i < k; i++) agg = fmaf(sw[i], g_inT[ss[i] * B_ + b], agg);
        row[b] = tanhf(fmaf(rj, agg, bj));
    }
}

// pass 2: only output nodes (dst<64); gather from inputs or state1
__global__ void __launch_bounds__(TPB) k_pass2(const float* __restrict__ bias,
                                               const float* __restrict__ resp,
                                               float* __restrict__ out) {
    int n = blockIdx.x;
    int t = threadIdx.x;
    if (!g_has_in[n]) {
        for (int b = t; b < B_; b += TPB) out[b * NOUT_ + n] = 0.f;
        return;
    }
    int k = g_p2_cnt[n]; if (k > MAXP2) k = MAXP2;
    __shared__ const float* sp[MAXP2];
    __shared__ float        sw[MAXP2];
    for (int i = t; i < k; i += TPB) {
        int s = g_p2_src[n * MAXP2 + i];
        sp[i] = (s < NI_) ? (g_inT    + (size_t)s * B_)
                          : (g_state1 + (size_t)g_node_slot[s - NI_] * B_);
        sw[i] = g_p2_w[n * MAXP2 + i];
    }
    __syncthreads();
    float bn = bias[n], rn = resp[n];
    for (int b = t; b < B_; b += TPB) {
        float agg = 0.f;
        for (int i = 0; i < k; i++) agg = fmaf(sw[i], sp[i][b], agg);
        out[b * NOUT_ + n] = tanhf(fmaf(rn, agg, bn));
    }
}

// ---------------- launch ----------------
extern "C" void kernel_launch(void* const* d_in, const int* in_sizes, int n_in,
                              void* d_out, int out_size) {
    const float* inputs  = (const float*)d_in[0];
    const float* weights = (const float*)d_in[1];
    const float* bias    = (const float*)d_in[2];
    const float* resp    = (const float*)d_in[3];
    const int*   src     = (const int*)d_in[4];
    const int*   dst     = (const int*)d_in[5];
    float*       out     = (float*)d_out;

    k_zero     <<<(NN_ + TPB - 1) / TPB, TPB>>>();
    k_transpose<<<(NI_ * B_ + TPB - 1) / TPB, TPB>>>(inputs);
    k_scan1    <<<(E_ + TPB - 1) / TPB, TPB>>>(src, dst, weights);
    k_compact  <<<(NN_ + TPB - 1) / TPB, TPB>>>();
    k_scan2    <<<(E_ + TPB - 1) / TPB, TPB>>>(src, dst, weights);
    k_pass1    <<<NN_, TPB>>>(bias, resp);
    k_pass2    <<<NOUT_, TPB>>>(bias, resp, out);
}

// round 2
// speedup vs baseline: 1.4120x; 1.4120x over previous
#include <cuda_runtime.h>
#include <math.h>

#define B_    1024
#define NI_   64
#define NN_   8256
#define E_    131072
#define NOUT_ 64
#define MAXP2 512      // per-output-node pass-2 edge cap (expected ~16)
#define MAXP1 64       // per-node pass-1 (src<NI) edge cap (expected ~0.12)
#define TPB   256

// ---------------- scratch (__device__ globals, zero-initialized at load) -------------
// Invariant: all flag/counter arrays are zero at kernel_launch entry. The pass
// kernels restore this invariant before finishing, so every graph replay sees
// the same initial state (no separate zeroing kernel needed).
__device__ int           g_p2_cnt[NOUT_];
__device__ int           g_p2_src[NOUT_ * MAXP2];
__device__ float         g_p2_w  [NOUT_ * MAXP2];
__device__ unsigned char g_needed[NN_];        // internal node is a pass-2 source
__device__ unsigned char g_has_in[NN_];        // node has any incoming edge
__device__ int           g_p1_cnt[NN_];
__device__ int           g_p1_src[NN_ * MAXP1];
__device__ float         g_p1_w  [NN_ * MAXP1];
__device__ __align__(16) float g_state1[(size_t)NN_ * B_];  // pass-1 activations [node][b]
__device__ __align__(16) float g_inT   [NI_ * B_];          // transposed inputs [feature][b]

// ---------------- K1: edge scan + input transpose (fused, independent work) ---------
__global__ void __launch_bounds__(TPB) k_scan(const float* __restrict__ in,
                                              const int*   __restrict__ src,
                                              const int*   __restrict__ dst,
                                              const float* __restrict__ w) {
    int e = blockIdx.x * blockDim.x + threadIdx.x;
    if (e < NI_ * B_) {                       // transpose: g_inT[c*B + r] = in[r*NI + c]
        int c = e / B_, r = e % B_;
        g_inT[e] = in[r * NI_ + c];
    }
    if (e < E_) {
        int d = dst[e];
        int s = src[e];
        g_has_in[d] = 1;
        if (d < NOUT_) {                      // pass-2 edge
            int pos = atomicAdd(&g_p2_cnt[d], 1);
            if (pos < MAXP2) {
                g_p2_src[d * MAXP2 + pos] = s;
                g_p2_w  [d * MAXP2 + pos] = w[e];
            }
            if (s >= NI_) g_needed[s - NI_] = 1;
        }
        if (s < NI_) {                        // pass-1 contributing edge (state0 == 0)
            int pos = atomicAdd(&g_p1_cnt[d], 1);
            if (pos < MAXP1) {
                g_p1_src[d * MAXP1 + pos] = s;
                g_p1_w  [d * MAXP1 + pos] = w[e];
            }
        }
    }
}

// ---------------- K2: pass 1 — state1 for needed nodes only -------------------------
__global__ void __launch_bounds__(TPB) k_pass1(const float* __restrict__ bias,
                                               const float* __restrict__ resp) {
    int j = blockIdx.x;            // node id (grid = NN_)
    int t = threadIdx.x;
    __shared__ int s_meta[3];      // need, has_in, cnt
    __shared__ int   ss[MAXP1];
    __shared__ float sw[MAXP1];
    if (t == 0) {
        s_meta[0] = g_needed[j];
        s_meta[1] = g_has_in[j];
        s_meta[2] = g_p1_cnt[j];
    }
    __syncthreads();
    int need = s_meta[0], has = s_meta[1];
    int k = s_meta[2]; if (k > MAXP1) k = MAXP1;
    if (need && has && t < k) {
        ss[t] = g_p1_src[j * MAXP1 + t];
        sw[t] = g_p1_w  [j * MAXP1 + t];
    }
    __syncthreads();
    // cleanup for next replay (only entries no later kernel reads)
    if (t == 0) {
        g_needed[j] = 0;
        g_p1_cnt[j] = 0;
        if (j >= NOUT_) g_has_in[j] = 0;   // has_in[<NOUT] is consumed+reset by pass2
    }
    if (!need) return;
    float4* row = (float4*)(g_state1 + (size_t)j * B_);
    if (!has) { row[t] = make_float4(0.f, 0.f, 0.f, 0.f); return; }
    float bj = bias[j], rj = resp[j];
    float4 agg = make_float4(0.f, 0.f, 0.f, 0.f);
    for (int i = 0; i < k; i++) {
        float4 v = ((const float4*)(g_inT + (size_t)ss[i] * B_))[t];
        float wi = sw[i];
        agg.x = fmaf(wi, v.x, agg.x);
        agg.y = fmaf(wi, v.y, agg.y);
        agg.z = fmaf(wi, v.z, agg.z);
        agg.w = fmaf(wi, v.w, agg.w);
    }
    float4 o;
    o.x = tanhf(fmaf(rj, agg.x, bj));
    o.y = tanhf(fmaf(rj, agg.y, bj));
    o.z = tanhf(fmaf(rj, agg.z, bj));
    o.w = tanhf(fmaf(rj, agg.w, bj));
    row[t] = o;
}

// ---------------- K3: pass 2 — only the 64 output nodes -----------------------------
__global__ void __launch_bounds__(TPB) k_pass2(const float* __restrict__ bias,
                                               const float* __restrict__ resp,
                                               float* __restrict__ out) {
    int n = blockIdx.x;            // output node (grid = NOUT_)
    int t = threadIdx.x;
    __shared__ int s_meta[2];
    __shared__ const float4* sp[MAXP2];
    __shared__ float         sw[MAXP2];
    if (t == 0) { s_meta[0] = g_has_in[n]; s_meta[1] = g_p2_cnt[n]; }
    __syncthreads();
    int has = s_meta[0];
    int k = s_meta[1]; if (k > MAXP2) k = MAXP2;
    if (has) {
        for (int i = t; i < k; i += TPB) {
            int s = g_p2_src[n * MAXP2 + i];
            sp[i] = (const float4*)((s < NI_) ? (g_inT    + (size_t)s          * B_)
                                              : (g_state1 + (size_t)(s - NI_) * B_));
            sw[i] = g_p2_w[n * MAXP2 + i];
        }
    }
    __syncthreads();
    if (t == 0) { g_has_in[n] = 0; g_p2_cnt[n] = 0; }   // cleanup (own entries only)
    int b0 = 4 * t;                                      // thread covers b0..b0+3
    if (!has) {
        out[(b0 + 0) * NOUT_ + n] = 0.f;
        out[(b0 + 1) * NOUT_ + n] = 0.f;
        out[(b0 + 2) * NOUT_ + n] = 0.f;
        out[(b0 + 3) * NOUT_ + n] = 0.f;
        return;
    }
    float bn = bias[n], rn = resp[n];
    float4 agg = make_float4(0.f, 0.f, 0.f, 0.f);
    for (int i = 0; i < k; i++) {
        float4 v = sp[i][t];
        float wi = sw[i];
        agg.x = fmaf(wi, v.x, agg.x);
        agg.y = fmaf(wi, v.y, agg.y);
        agg.z = fmaf(wi, v.z, agg.z);
        agg.w = fmaf(wi, v.w, agg.w);
    }
    out[(b0 + 0) * NOUT_ + n] = tanhf(fmaf(rn, agg.x, bn));
    out[(b0 + 1) * NOUT_ + n] = tanhf(fmaf(rn, agg.y, bn));
    out[(b0 + 2) * NOUT_ + n] = tanhf(fmaf(rn, agg.z, bn));
    out[(b0 + 3) * NOUT_ + n] = tanhf(fmaf(rn, agg.w, bn));
}

// ---------------- launch ----------------
extern "C" void kernel_launch(void* const* d_in, const int* in_sizes, int n_in,
                              void* d_out, int out_size) {
    const float* inputs  = (const float*)d_in[0];
    const float* weights = (const float*)d_in[1];
    const float* bias    = (const float*)d_in[2];
    const float* resp    = (const float*)d_in[3];
    const int*   src     = (const int*)d_in[4];
    const int*   dst     = (const int*)d_in[5];
    float*       out     = (float*)d_out;

    k_scan <<<(E_ + TPB - 1) / TPB, TPB>>>(inputs, src, dst, weights);
    k_pass1<<<NN_,   TPB>>>(bias, resp);
    k_pass2<<<NOUT_, TPB>>>(bias, resp, out);
}

// round 3
// speedup vs baseline: 1.5193x; 1.0760x over previous
#include <cuda_runtime.h>
#include <math.h>

#define B_    1024
#define NI_   64
#define NN_   8256
#define E_    131072
#define NOUT_ 64
#define MAXP2 512      // per-output-node pass-2 edge cap (expected ~16, max ~35)
#define MAXP1 64       // per-node input-edge cap (expected ~0.12, max ~5)
#define G1    1024     // pass-1 grid (needed count expected ~950)
#define TPBS  128      // k_scan block
#define TPB   256      // pass block

// -------- scratch (__device__ globals, zero-initialized at load) --------
// Invariant: flag/counter arrays are zero at kernel_launch entry; k_pass2
// restores the invariant each replay. cmode/cval/state1 need no reset: they
// are fully rewritten for every node that is subsequently read.
__device__ int   g_p2_cnt[NOUT_];
__device__ int   g_p2_src[NOUT_ * MAXP2];
__device__ float g_p2_w  [NOUT_ * MAXP2];
__device__ int   g_needed_i[NN_];          // dedupe flags (reset by pass2)
__device__ int   g_needed_list[NN_];
__device__ int   g_needed_cnt;
__device__ unsigned char g_has_in[NN_];
__device__ int   g_p1_cnt[NN_];
__device__ int   g_p1_src[NN_ * MAXP1];
__device__ float g_p1_w  [NN_ * MAXP1];
__device__ unsigned char g_cmode[NN_];     // 1: pass-1 activation is scalar g_cval
__device__ float g_cval [NN_];
__device__ __align__(16) float g_state1[(size_t)NN_ * B_];  // row-mode activations
__device__ __align__(16) float g_inT   [NI_ * B_];          // inputs transposed [f][b]

// -------- K1: vectorized edge scan + input transpose --------
__device__ __forceinline__ void scan_edge(int e, int d, int s,
                                          const float* __restrict__ w) {
    g_has_in[d] = 1;
    if (d < NOUT_) {                          // pass-2 edge
        int pos = atomicAdd(&g_p2_cnt[d], 1);
        if (pos < MAXP2) {
            g_p2_src[d * MAXP2 + pos] = s;
            g_p2_w  [d * MAXP2 + pos] = w[e];
        }
        if (s >= NI_) {                       // mark + compact needed internal src
            int j = s - NI_;
            if (atomicExch(&g_needed_i[j], 1) == 0) {
                int slot = atomicAdd(&g_needed_cnt, 1);
                g_needed_list[slot] = j;
            }
        }
    }
    if (s < NI_) {                            // pass-1 contributing edge (state0==0)
        int pos = atomicAdd(&g_p1_cnt[d], 1);
        if (pos < MAXP1) {
            g_p1_src[d * MAXP1 + pos] = s;
            g_p1_w  [d * MAXP1 + pos] = w[e];
        }
    }
}

__global__ void __launch_bounds__(TPBS) k_scan(const float* __restrict__ in,
                                               const int*   __restrict__ src,
                                               const int*   __restrict__ dst,
                                               const float* __restrict__ w) {
    int tid = blockIdx.x * TPBS + threadIdx.x;     // 0..32767 (E_/4 threads)
    int4 d4 = ((const int4*)dst)[tid];
    int4 s4 = ((const int4*)src)[tid];
    // transpose: g_inT[c*B+r] = in[r*NI+c]; 2 elements per thread
    int i0 = tid, i1 = tid + (E_ / 4);
    float t0 = in[(i0 % B_) * NI_ + i0 / B_];
    float t1 = in[(i1 % B_) * NI_ + i1 / B_];
    g_inT[i0] = t0;
    g_inT[i1] = t1;
    int e0 = tid * 4;
    scan_edge(e0 + 0, d4.x, s4.x, w);
    scan_edge(e0 + 1, d4.y, s4.y, w);
    scan_edge(e0 + 2, d4.z, s4.z, w);
    scan_edge(e0 + 3, d4.w, s4.w, w);
}

// -------- K2: pass 1 over compacted needed list --------
__global__ void __launch_bounds__(TPB) k_pass1(const float* __restrict__ bias,
                                               const float* __restrict__ resp) {
    __shared__ int   meta[2];
    __shared__ int   ss[MAXP1];
    __shared__ float sw[MAXP1];
    int t = threadIdx.x;
    int cnt = g_needed_cnt;
    for (int slot = blockIdx.x; slot < cnt; slot += G1) {
        int j = g_needed_list[slot];
        if (t == 0) { meta[0] = g_has_in[j]; meta[1] = g_p1_cnt[j]; }
        __syncthreads();
        int has = meta[0];
        int k = meta[1]; if (k > MAXP1) k = MAXP1;
        if (!has) {
            if (t == 0) { g_cval[j] = 0.f; g_cmode[j] = 1; }
        } else if (k == 0) {
            if (t == 0) { g_cval[j] = tanhf(bias[j]); g_cmode[j] = 1; }
        } else {
            if (t < k) { ss[t] = g_p1_src[j * MAXP1 + t]; sw[t] = g_p1_w[j * MAXP1 + t]; }
            if (t == 0) g_cmode[j] = 0;
            __syncthreads();
            float bj = bias[j], rj = resp[j];
            float4 agg = make_float4(0.f, 0.f, 0.f, 0.f);
            for (int i = 0; i < k; i++) {
                float4 v = ((const float4*)(g_inT + (size_t)ss[i] * B_))[t];
                float wi = sw[i];
                agg.x = fmaf(wi, v.x, agg.x);
                agg.y = fmaf(wi, v.y, agg.y);
                agg.z = fmaf(wi, v.z, agg.z);
                agg.w = fmaf(wi, v.w, agg.w);
            }
            float4 o;
            o.x = tanhf(fmaf(rj, agg.x, bj));
            o.y = tanhf(fmaf(rj, agg.y, bj));
            o.z = tanhf(fmaf(rj, agg.z, bj));
            o.w = tanhf(fmaf(rj, agg.w, bj));
            ((float4*)(g_state1 + (size_t)j * B_))[t] = o;
        }
        __syncthreads();   // smem reuse guard for next slot
    }
}

// -------- K3: pass 2 (64 output nodes) + scratch cleanup --------
__global__ void __launch_bounds__(TPB) k_pass2(const float* __restrict__ bias,
                                               const float* __restrict__ resp,
                                               float* __restrict__ out) {
    int n = blockIdx.x, t = threadIdx.x;
    __shared__ int   s_meta[2];
    __shared__ float s_const;
    __shared__ int   s_nrow;
    __shared__ const float4* sp[MAXP2];
    __shared__ float         sw[MAXP2];
    if (t == 0) { s_meta[0] = g_has_in[n]; s_meta[1] = g_p2_cnt[n];
                  s_const = 0.f; s_nrow = 0; }
    __syncthreads();
    int has = s_meta[0];
    int k = s_meta[1]; if (k > MAXP2) k = MAXP2;
    if (has) {
        for (int i = t; i < k; i += TPB) {
            int   s  = g_p2_src[n * MAXP2 + i];
            float wi = g_p2_w  [n * MAXP2 + i];
            if (s >= NI_ && g_cmode[s - NI_]) {
                atomicAdd(&s_const, wi * g_cval[s - NI_]);
            } else {
                int pos = atomicAdd(&s_nrow, 1);
                sp[pos] = (const float4*)((s < NI_)
                              ? (g_inT    + (size_t)s          * B_)
                              : (g_state1 + (size_t)(s - NI_) * B_));
                sw[pos] = wi;
            }
        }
    }
    __syncthreads();
    // cleanup: restore zero-invariant for next graph replay
    int gtid = n * TPB + t;                       // 0..16383 >= NN_
    if (gtid < NN_) {
        g_needed_i[gtid] = 0;
        g_p1_cnt[gtid]   = 0;
        if (gtid >= NOUT_) g_has_in[gtid] = 0;
    }
    if (t == 0) { g_has_in[n] = 0; g_p2_cnt[n] = 0; }
    if (gtid == 0) g_needed_cnt = 0;

    int b0 = 4 * t;
    if (!has) {
        out[(b0 + 0) * NOUT_ + n] = 0.f;
        out[(b0 + 1) * NOUT_ + n] = 0.f;
        out[(b0 + 2) * NOUT_ + n] = 0.f;
        out[(b0 + 3) * NOUT_ + n] = 0.f;
        return;
    }
    int   nr = s_nrow;
    float rn = resp[n];
    float bn = fmaf(rn, s_const, bias[n]);        // fold const sources into bias
    float4 agg = make_float4(0.f, 0.f, 0.f, 0.f);
    for (int i = 0; i < nr; i++) {
        float4 v = sp[i][t];
        float wi = sw[i];
        agg.x = fmaf(wi, v.x, agg.x);
        agg.y = fmaf(wi, v.y, agg.y);
        agg.z = fmaf(wi, v.z, agg.z);
        agg.w = fmaf(wi, v.w, agg.w);
    }
    out[(b0 + 0) * NOUT_ + n] = tanhf(fmaf(rn, agg.x, bn));
    out[(b0 + 1) * NOUT_ + n] = tanhf(fmaf(rn, agg.y, bn));
    out[(b0 + 2) * NOUT_ + n] = tanhf(fmaf(rn, agg.z, bn));
    out[(b0 + 3) * NOUT_ + n] = tanhf(fmaf(rn, agg.w, bn));
}

// -------- launch --------
extern "C" void kernel_launch(void* const* d_in, const int* in_sizes, int n_in,
                              void* d_out, int out_size) {
    const float* inputs  = (const float*)d_in[0];
    const float* weights = (const float*)d_in[1];
    const float* bias    = (const float*)d_in[2];
    const float* resp    = (const float*)d_in[3];
    const int*   src     = (const int*)d_in[4];
    const int*   dst     = (const int*)d_in[5];
    float*       out     = (float*)d_out;

    k_scan <<<(E_ / 4) / TPBS, TPBS>>>(inputs, src, dst, weights);
    k_pass1<<<G1,    TPB>>>(bias, resp);
    k_pass2<<<NOUT_, TPB>>>(bias, resp, out);
}